// round 2
// baseline (speedup 1.0000x reference)
#include <cuda_runtime.h>

// Problem constants (from reference): WIDTH=1024, HALF=512, DEPTH=32, BATCH=32768.
#define HALF_W 512
#define DEPTH_N 32

// Scratch for the collapsed butterfly eigenvalues: half_p[j] = 0.5 * prod_i (1 - 2*params[j][i]).
// __device__ global array (no allocation — harness allocation guards forbid cudaMalloc).
__device__ float g_half_p[HALF_W];

// Kernel 1: tiny precompute. One block, 512 threads; each thread reduces its 32 depth weights.
// Math: each depth step applies [[1-w, w],[w, 1-w]] = (1-w)I + wJ to pair (j, j+512).
// All steps for a given j commute; in the (s,d) = (x0+x1, x0-x1) eigenbasis the product
// has eigenvalue 1 on s and p_j = prod_i (1 - 2*w_ij) on d.
__global__ void butterfly_precompute_kernel(const float* __restrict__ params) {
    int j = threadIdx.x;
    if (j < HALF_W) {
        const float* row = params + j * DEPTH_N;   // params is [HALF][DEPTH] row-major
        float p = 1.0f;
#pragma unroll
        for (int i = 0; i < DEPTH_N; ++i) {
            p *= fmaf(-2.0f, row[i], 1.0f);        // (1 - 2*w)
        }
        g_half_p[j] = 0.5f * p;
    }
}

// Kernel 2: streaming pass.
// out0 = 0.5*s + half_p * d ; out1 = 0.5*s - half_p * d  with s = x0+x1, d = x0-x1.
// One thread handles 4 pairs via float4. Each row has 512 pairs = 128 float4 slots.
// linear idx -> (row, slot); a warp covers 32 consecutive slots in one row, so the
// x0 load (row base + slot*16B) and the x1 load (row base + 2KB + slot*16B) are each
// fully coalesced 128B-segment streams. Same for the two stores.
__global__ void __launch_bounds__(256, 8)
butterfly_apply_kernel(const float* __restrict__ X, float* __restrict__ out, int n_vec4) {
    const int idx  = blockIdx.x * blockDim.x + threadIdx.x;   // 0 .. BATCH*128-1
    if (idx >= n_vec4) return;
    const int slot = idx & 127;                               // float4 slot within row
    const int row  = idx >> 7;

    const float4* x0p = reinterpret_cast<const float4*>(X + (size_t)row * 1024) + slot;
    const float4* x1p = reinterpret_cast<const float4*>(X + (size_t)row * 1024 + HALF_W) + slot;
    float4*       o0p = reinterpret_cast<float4*>(out + (size_t)row * 1024) + slot;
    float4*       o1p = reinterpret_cast<float4*>(out + (size_t)row * 1024 + HALF_W) + slot;

    float4 x0 = *x0p;
    float4 x1 = *x1p;
    // half_p table: 2KB total, L1-resident after first wave; read-only.
    float4 hp = reinterpret_cast<const float4*>(g_half_p)[slot];

    float4 o0, o1;
    {
        float hs, t;
        hs = 0.5f * (x0.x + x1.x); t = hp.x * (x0.x - x1.x); o0.x = hs + t; o1.x = hs - t;
        hs = 0.5f * (x0.y + x1.y); t = hp.y * (x0.y - x1.y); o0.y = hs + t; o1.y = hs - t;
        hs = 0.5f * (x0.z + x1.z); t = hp.z * (x0.z - x1.z); o0.z = hs + t; o1.z = hs - t;
        hs = 0.5f * (x0.w + x1.w); t = hp.w * (x0.w - x1.w); o0.w = hs + t; o1.w = hs - t;
    }

    *o0p = o0;
    *o1p = o1;
}

extern "C" void kernel_launch(void* const* d_in, const int* in_sizes, int n_in,
                              void* d_out, int out_size) {
    const float* X      = (const float*)d_in[0];   // [32768, 1024] fp32
    const float* params = (const float*)d_in[1];   // [512, 32] fp32
    float* out          = (float*)d_out;           // [32768, 1024] fp32

    butterfly_precompute_kernel<<<1, HALF_W>>>(params);

    // out_size = BATCH*1024 elements; 8 elements (two float4s) per thread.
    const int n_vec4 = out_size / 8;               // threads needed
    const int blocks = (n_vec4 + 255) / 256;
    butterfly_apply_kernel<<<blocks, 256>>>(X, out, n_vec4);
}

// round 3
// speedup vs baseline: 1.1806x; 1.1806x over previous
#include <cuda_runtime.h>

// Problem constants (from reference): WIDTH=1024, HALF=512, DEPTH=32, BATCH=32768.
#define HALF_W 512
#define DEPTH_N 32
#define PRE_BLOCKS 2
#define PRE_ROWS   (HALF_W / PRE_BLOCKS)   // 256 rows per block
#define PAD_STRIDE 33                      // 32 + 1 padding -> conflict-free column reads

// Scratch for the collapsed butterfly eigenvalues: half_p[j] = 0.5 * prod_i (1 - 2*params[j][i]).
// __device__ global array (no allocation — harness allocation guards forbid cudaMalloc).
__device__ float g_half_p[HALF_W];

// Kernel 1: precompute p_j = prod_i (1 - 2*w_ij).
// Math: each depth step applies [[1-w, w],[w, 1-w]] = (1-w)I + wJ to pair (j, j+512).
// All steps for a given j commute; in the (s,d) = (x0+x1, x0-x1) eigenbasis the product
// has eigenvalue 1 on s and p_j on d.
//
// R2 post-mortem fix: the old version had thread j read row j directly from GMEM
// (stride-128B across the warp -> 32 L1tex wavefronts per LDG, ~15us on one SM).
// Now: coalesced float4 loads into padded smem, then conflict-free row products.
__global__ void butterfly_precompute_kernel(const float* __restrict__ params) {
    __shared__ float sp[PRE_ROWS * PAD_STRIDE];   // 256*33*4 = 33.8 KB

    const int t = threadIdx.x;                    // 0..255
    const int b = blockIdx.x;                     // 0..1

    // Phase 1: coalesced load of this block's slice (256 rows x 32 floats = 2048 float4s).
    const float4* src = reinterpret_cast<const float4*>(params) + b * (PRE_ROWS * DEPTH_N / 4);
#pragma unroll
    for (int k = 0; k < 8; ++k) {
        int idx = t + k * 256;                    // float4 index within slice, coalesced
        float4 v = src[idx];
        int j_local = idx >> 3;                   // row within slice (8 float4s per row)
        int m       = idx & 7;                    // float4 slot within row
        float* dst = sp + j_local * PAD_STRIDE + m * 4;
        dst[0] = v.x; dst[1] = v.y; dst[2] = v.z; dst[3] = v.w;
    }
    __syncthreads();

    // Phase 2: thread t reduces row t. bank(t*33+i) = (t+i) mod 32 -> conflict-free.
    const float* row = sp + t * PAD_STRIDE;
    float p = 1.0f;
#pragma unroll
    for (int i = 0; i < DEPTH_N; ++i) {
        p *= fmaf(-2.0f, row[i], 1.0f);           // (1 - 2*w)
    }
    g_half_p[b * PRE_ROWS + t] = 0.5f * p;
}

// Kernel 2: streaming pass (unchanged from R2 — at the DRAM roofline: 75.6% DRAM, 5982 GB/s).
// out0 = 0.5*s + half_p * d ; out1 = 0.5*s - half_p * d  with s = x0+x1, d = x0-x1.
// One thread handles 4 pairs via float4. Each row has 512 pairs = 128 float4 slots.
// A warp covers 32 consecutive slots in one row, so the x0 load (row base + slot*16B)
// and the x1 load (row base + 2KB + slot*16B) are each fully coalesced 128B-segment
// streams. Same for the two stores.
__global__ void __launch_bounds__(256, 8)
butterfly_apply_kernel(const float* __restrict__ X, float* __restrict__ out, int n_vec4) {
    const int idx  = blockIdx.x * blockDim.x + threadIdx.x;   // 0 .. BATCH*128-1
    if (idx >= n_vec4) return;
    const int slot = idx & 127;                               // float4 slot within row
    const int row  = idx >> 7;

    const float4* x0p = reinterpret_cast<const float4*>(X + (size_t)row * 1024) + slot;
    const float4* x1p = reinterpret_cast<const float4*>(X + (size_t)row * 1024 + HALF_W) + slot;
    float4*       o0p = reinterpret_cast<float4*>(out + (size_t)row * 1024) + slot;
    float4*       o1p = reinterpret_cast<float4*>(out + (size_t)row * 1024 + HALF_W) + slot;

    float4 x0 = *x0p;
    float4 x1 = *x1p;
    // half_p table: 2KB total, L1-resident after first wave; read-only.
    float4 hp = reinterpret_cast<const float4*>(g_half_p)[slot];

    float4 o0, o1;
    {
        float hs, t;
        hs = 0.5f * (x0.x + x1.x); t = hp.x * (x0.x - x1.x); o0.x = hs + t; o1.x = hs - t;
        hs = 0.5f * (x0.y + x1.y); t = hp.y * (x0.y - x1.y); o0.y = hs + t; o1.y = hs - t;
        hs = 0.5f * (x0.z + x1.z); t = hp.z * (x0.z - x1.z); o0.z = hs + t; o1.z = hs - t;
        hs = 0.5f * (x0.w + x1.w); t = hp.w * (x0.w - x1.w); o0.w = hs + t; o1.w = hs - t;
    }

    *o0p = o0;
    *o1p = o1;
}

extern "C" void kernel_launch(void* const* d_in, const int* in_sizes, int n_in,
                              void* d_out, int out_size) {
    const float* X      = (const float*)d_in[0];   // [32768, 1024] fp32
    const float* params = (const float*)d_in[1];   // [512, 32] fp32
    float* out          = (float*)d_out;           // [32768, 1024] fp32

    butterfly_precompute_kernel<<<PRE_BLOCKS, PRE_ROWS>>>(params);

    // out_size = BATCH*1024 elements; 8 elements (two float4s) per thread.
    const int n_vec4 = out_size / 8;               // threads needed
    const int blocks = (n_vec4 + 255) / 256;
    butterfly_apply_kernel<<<blocks, 256>>>(X, out, n_vec4);
}

// round 4
// speedup vs baseline: 1.2362x; 1.0471x over previous
#include <cuda_runtime.h>

// Problem constants (from reference): WIDTH=1024, HALF=512, DEPTH=32, BATCH=32768.
// Row layout: 1024 floats = 256 float4; x0 = slots [0,128), x1 = slots [128,256).
// Math: each depth step applies [[1-w,w],[w,1-w]] = (1-w)I + wJ to pair (j, j+512).
// All steps for a given j commute; in the (s,d)=(x0+x1, x0-x1) eigenbasis the 32-step
// product has eigenvalue 1 on s and p_j = prod_i(1-2*w_ij) on d:
//   out0 = 0.5*s + (0.5*p_j)*d ;  out1 = 0.5*s - (0.5*p_j)*d
//
// Fused single kernel (R4): grid remapped to (slot-group, row-chunk) so each block
// needs only 32 p_j values -> one cooperative 4KB coalesced params read per block
// (only 16 distinct slices chip-wide -> L2-resident) + shfl product-reduce.
// Removes the separate precompute kernel and the serialized inter-kernel gap
// (~9.7us in R3).

#define GROUPS_PER_ROW 16   // 128 float4 slots / 8 slots per group
#define SLOTS_PER_GRP  8    // 8 float4 slots = 32 pairs per group
#define ROWS_PER_CHUNK 32

__global__ void __launch_bounds__(256, 8)
butterfly_fused_kernel(const float* __restrict__ X, const float* __restrict__ params,
                       float* __restrict__ out, int n_rows) {
    __shared__ float shp[32];   // 0.5 * p_j for this block's 32 pair indices

    const int tid   = threadIdx.x;                 // 0..255
    const int group = blockIdx.x & (GROUPS_PER_ROW - 1);   // slot group 0..15
    const int chunk = blockIdx.x >> 4;                     // row chunk

    // ---- Prologue: cooperative p for pairs [group*32, group*32+32) ----
    // params slice = rows [group*32, group*32+32) = float4s [group*256, group*256+256).
    // Thread t loads float4 t of the slice (fully coalesced, 4KB, L2-resident).
    {
        float4 w = reinterpret_cast<const float4*>(params)[group * 256 + tid];
        float q = fmaf(-2.0f, w.x, 1.0f) * fmaf(-2.0f, w.y, 1.0f)
                * fmaf(-2.0f, w.z, 1.0f) * fmaf(-2.0f, w.w, 1.0f);
        // Each params row (32 floats) = 8 consecutive threads; product-reduce within
        // the 8-thread segment (segments never cross a warp since 8 | 32).
        q *= __shfl_xor_sync(0xFFFFFFFF, q, 1);
        q *= __shfl_xor_sync(0xFFFFFFFF, q, 2);
        q *= __shfl_xor_sync(0xFFFFFFFF, q, 4);
        if ((tid & 7) == 0) shp[tid >> 3] = 0.5f * q;   // local pair-row index 0..31
    }
    __syncthreads();

    // ---- Streaming butterfly ----
    const int s_in = tid & (SLOTS_PER_GRP - 1);    // slot within group, 0..7
    const int r_in = tid >> 3;                     // row within chunk, 0..31
    const int row  = chunk * ROWS_PER_CHUNK + r_in;
    if (row >= n_rows) return;
    const int slot = group * SLOTS_PER_GRP + s_in; // 0..127

    // Warp = 8 consecutive slots x 4 consecutive rows -> every 32-lane access
    // touches exactly 4 full 128B lines (same coalescing as the R3 kernel).
    const float4* x0p = reinterpret_cast<const float4*>(X   + (size_t)row * 1024) + slot;
    const float4* x1p = reinterpret_cast<const float4*>(X   + (size_t)row * 1024 + 512) + slot;
    float4*       o0p = reinterpret_cast<float4*>(out + (size_t)row * 1024) + slot;
    float4*       o1p = reinterpret_cast<float4*>(out + (size_t)row * 1024 + 512) + slot;

    float4 x0 = *x0p;
    float4 x1 = *x1p;
    // 4 half-p values for this slot: LDS.128, 8 distinct 16B regions spanning all
    // banks -> conflict-free; threads sharing s_in broadcast.
    float4 hp = reinterpret_cast<const float4*>(shp)[s_in];

    float4 o0, o1;
    {
        float hs, t;
        hs = 0.5f * (x0.x + x1.x); t = hp.x * (x0.x - x1.x); o0.x = hs + t; o1.x = hs - t;
        hs = 0.5f * (x0.y + x1.y); t = hp.y * (x0.y - x1.y); o0.y = hs + t; o1.y = hs - t;
        hs = 0.5f * (x0.z + x1.z); t = hp.z * (x0.z - x1.z); o0.z = hs + t; o1.z = hs - t;
        hs = 0.5f * (x0.w + x1.w); t = hp.w * (x0.w - x1.w); o0.w = hs + t; o1.w = hs - t;
    }

    *o0p = o0;
    *o1p = o1;
}

extern "C" void kernel_launch(void* const* d_in, const int* in_sizes, int n_in,
                              void* d_out, int out_size) {
    const float* X      = (const float*)d_in[0];   // [32768, 1024] fp32
    const float* params = (const float*)d_in[1];   // [512, 32] fp32
    float* out          = (float*)d_out;           // [32768, 1024] fp32

    const int n_rows = out_size / 1024;            // 32768
    // blocks = 16 groups * ceil(n_rows/32) chunks
    const int chunks = (n_rows + ROWS_PER_CHUNK - 1) / ROWS_PER_CHUNK;
    butterfly_fused_kernel<<<GROUPS_PER_ROW * chunks, 256>>>(X, params, out, n_rows);
}

// round 8
// speedup vs baseline: 1.2417x; 1.0044x over previous
#include <cuda_runtime.h>

// Problem constants (from reference): WIDTH=1024, HALF=512, DEPTH=32, BATCH=32768.
// Row layout: 1024 floats = 256 float4; x0 = slots [0,128), x1 = slots [128,256).
// Math: each depth step applies [[1-w,w],[w,1-w]] = (1-w)I + wJ to pair (j, j+512).
// All steps for a given j commute; in the (s,d)=(x0+x1, x0-x1) eigenbasis the 32-step
// product has eigenvalue 1 on s and p_j = prod_i(1-2*w_ij) on d:
//   out0 = 0.5*s + (0.5*p_j)*d ;  out1 = 0.5*s - (0.5*p_j)*d
//
// R5 changes vs R4 (which ran 37.2us @ DRAM 72.9%):
//  - X loads issued BEFORE the params prologue (prologue latency hides under them)
//  - 512-thread blocks / 64 rows per chunk -> half the prologues & barriers
//  - __ldcs/__stcs streaming hints (touch-once data, evict-first)

#define GROUPS_PER_ROW 16   // 128 float4 slots / 8 slots per group
#define SLOTS_PER_GRP  8    // 8 float4 slots = 32 pairs per group
#define ROWS_PER_CHUNK 64
#define BLOCK_THREADS  512

__global__ void __launch_bounds__(BLOCK_THREADS, 4)
butterfly_fused_kernel(const float* __restrict__ X, const float* __restrict__ params,
                       float* __restrict__ out, int n_rows) {
    __shared__ float shp[32];   // 0.5 * p_j for this block's 32 pair indices

    const int tid   = threadIdx.x;                         // 0..511
    const int group = blockIdx.x & (GROUPS_PER_ROW - 1);   // slot group 0..15
    const int chunk = blockIdx.x >> 4;                     // row chunk

    // ---- Addressing: warp = 8 consecutive slots x 4 consecutive rows ----
    const int s_in = tid & (SLOTS_PER_GRP - 1);            // slot within group, 0..7
    const int r_in = tid >> 3;                             // row within chunk, 0..63
    const int row  = chunk * ROWS_PER_CHUNK + r_in;
    const bool active = (row < n_rows);
    const int slot = group * SLOTS_PER_GRP + s_in;         // 0..127

    const float4* x0p = reinterpret_cast<const float4*>(X   + (size_t)row * 1024) + slot;
    const float4* x1p = reinterpret_cast<const float4*>(X   + (size_t)row * 1024 + 512) + slot;
    float4*       o0p = reinterpret_cast<float4*>(out + (size_t)row * 1024) + slot;
    float4*       o1p = reinterpret_cast<float4*>(out + (size_t)row * 1024 + 512) + slot;

    // Issue the streaming loads FIRST; the prologue below hides under their latency.
    float4 x0, x1;
    if (active) {
        x0 = __ldcs(x0p);
        x1 = __ldcs(x1p);
    }

    // ---- Prologue: cooperative p for pairs [group*32, group*32+32) ----
    // params slice = rows [group*32, group*32+32) = float4s [group*256, group*256+256).
    // First 256 threads each load one float4 (fully coalesced 4KB, L2-resident since
    // only 16 distinct slices exist chip-wide).
    if (tid < 256) {
        float4 w = __ldg(reinterpret_cast<const float4*>(params) + group * 256 + tid);
        float q = fmaf(-2.0f, w.x, 1.0f) * fmaf(-2.0f, w.y, 1.0f)
                * fmaf(-2.0f, w.z, 1.0f) * fmaf(-2.0f, w.w, 1.0f);
        // Each params row (32 floats) = 8 consecutive threads; product-reduce within
        // the 8-thread segment (segments never cross a warp since 8 | 32).
        q *= __shfl_xor_sync(0xFFFFFFFF, q, 1);
        q *= __shfl_xor_sync(0xFFFFFFFF, q, 2);
        q *= __shfl_xor_sync(0xFFFFFFFF, q, 4);
        if ((tid & 7) == 0) shp[tid >> 3] = 0.5f * q;      // local pair index 0..31
    }
    __syncthreads();

    if (!active) return;

    // 4 half-p values for this slot: LDS.128, 8 distinct 16B regions spanning all
    // banks -> conflict-free; threads sharing s_in broadcast.
    float4 hp = reinterpret_cast<const float4*>(shp)[s_in];

    float4 o0, o1;
    {
        float hs, t;
        hs = 0.5f * (x0.x + x1.x); t = hp.x * (x0.x - x1.x); o0.x = hs + t; o1.x = hs - t;
        hs = 0.5f * (x0.y + x1.y); t = hp.y * (x0.y - x1.y); o0.y = hs + t; o1.y = hs - t;
        hs = 0.5f * (x0.z + x1.z); t = hp.z * (x0.z - x1.z); o0.z = hs + t; o1.z = hs - t;
        hs = 0.5f * (x0.w + x1.w); t = hp.w * (x0.w - x1.w); o0.w = hs + t; o1.w = hs - t;
    }

    __stcs(o0p, o0);
    __stcs(o1p, o1);
}

extern "C" void kernel_launch(void* const* d_in, const int* in_sizes, int n_in,
                              void* d_out, int out_size) {
    const float* X      = (const float*)d_in[0];   // [32768, 1024] fp32
    const float* params = (const float*)d_in[1];   // [512, 32] fp32
    float* out          = (float*)d_out;           // [32768, 1024] fp32

    const int n_rows = out_size / 1024;            // 32768
    const int chunks = (n_rows + ROWS_PER_CHUNK - 1) / ROWS_PER_CHUNK;
    butterfly_fused_kernel<<<GROUPS_PER_ROW * chunks, BLOCK_THREADS>>>(X, params, out, n_rows);
}